// round 8
// baseline (speedup 1.0000x reference)
#include <cuda_runtime.h>
#include <cuda_fp16.h>
#include <cstdint>

#define NN   8192
#define FIN  256
#define FOUT 128
#define NC   128        // j-chunks of 64
#define BM   32         // rows per CTA in main kernel
#define GRID_MAIN (NN / BM)   // 256

// ---------------- scratch (static device globals; no allocation) ----------------
__device__ __align__(16) __half g_Wh16[(size_t)NN * FOUT];  // [row j][col c] fp16
__device__ __align__(16) float g_nf1[NN];   // -f1
__device__ __align__(16) float g_H1 [NN];   // exp(-0.8 f1)
__device__ __align__(16) float g_f2 [NN];
__device__ __align__(16) float g_E2 [NN];   // exp(f2)
__device__ __align__(16) float g_G2 [NN];   // exp(0.2 f2)

__device__ __forceinline__ uint32_t sptr(const void* p) {
    return (uint32_t)__cvta_generic_to_shared(p);
}

// =====================================================================
// Kernel 1: Wh = h @ W (fp32 SIMT GEMM) fused with fp16 output and the
// f1/f2 row reductions + exp vectors. grid 256, block 256, 2 CTAs/SM.
// =====================================================================
__global__ __launch_bounds__(256, 2) void wh_gemm_kernel(
    const float* __restrict__ h, const float* __restrict__ Wm,
    const float* __restrict__ a)
{
    __shared__ float hs[32][33];
    __shared__ float Ws[32][132];
    const int tid = threadIdx.x;
    const int i0  = blockIdx.x * 32;
    const int ty  = tid >> 4, tx = tid & 15;

    float acc[2][8];
#pragma unroll
    for (int u = 0; u < 2; u++)
#pragma unroll
        for (int v = 0; v < 8; v++) acc[u][v] = 0.0f;

    for (int k0 = 0; k0 < FIN; k0 += 32) {
        __syncthreads();
        {   int r = tid >> 3, c = (tid & 7) * 4;
            float4 v = *(const float4*)&h[(size_t)(i0 + r) * FIN + k0 + c];
            hs[r][c+0]=v.x; hs[r][c+1]=v.y; hs[r][c+2]=v.z; hs[r][c+3]=v.w;
        }
        {   int r = tid >> 3, c = (tid & 7) * 16;
#pragma unroll
            for (int q = 0; q < 4; q++) {
                float4 v = *(const float4*)&Wm[(size_t)(k0 + r) * FOUT + c + 4*q];
                Ws[r][c+4*q+0]=v.x; Ws[r][c+4*q+1]=v.y; Ws[r][c+4*q+2]=v.z; Ws[r][c+4*q+3]=v.w;
            }
        }
        __syncthreads();
#pragma unroll 8
        for (int k = 0; k < 32; k++) {
            float a0 = hs[2*ty][k], a1 = hs[2*ty+1][k];
            float4 b0 = *(const float4*)&Ws[k][8*tx];
            float4 b1 = *(const float4*)&Ws[k][8*tx + 4];
            float bv[8] = {b0.x,b0.y,b0.z,b0.w,b1.x,b1.y,b1.z,b1.w};
#pragma unroll
            for (int v = 0; v < 8; v++) {
                acc[0][v] = fmaf(a0, bv[v], acc[0][v]);
                acc[1][v] = fmaf(a1, bv[v], acc[1][v]);
            }
        }
    }

    float f1a[2] = {0.f, 0.f}, f2a[2] = {0.f, 0.f};
#pragma unroll
    for (int u = 0; u < 2; u++) {
        int row = i0 + 2*ty + u;
#pragma unroll
        for (int q = 0; q < 4; q++) {
            *(__half2*)&g_Wh16[(size_t)row * FOUT + 8*tx + 2*q] =
                __floats2half2_rn(acc[u][2*q], acc[u][2*q+1]);
        }
#pragma unroll
        for (int v = 0; v < 8; v++) {
            int col = 8*tx + v;
            f1a[u] = fmaf(acc[u][v], a[col],        f1a[u]);
            f2a[u] = fmaf(acc[u][v], a[FOUT + col], f2a[u]);
        }
    }
#pragma unroll
    for (int o = 8; o > 0; o >>= 1) {
        f1a[0] += __shfl_xor_sync(0xffffffffu, f1a[0], o);
        f1a[1] += __shfl_xor_sync(0xffffffffu, f1a[1], o);
        f2a[0] += __shfl_xor_sync(0xffffffffu, f2a[0], o);
        f2a[1] += __shfl_xor_sync(0xffffffffu, f2a[1], o);
    }
    if (tx == 0) {
#pragma unroll
        for (int u = 0; u < 2; u++) {
            int i = i0 + 2*ty + u;
            float f1 = f1a[u], f2 = f2a[u];
            g_nf1[i] = -f1;
            g_H1[i]  = expf(-0.8f * f1);
            g_f2[i]  = f2;
            g_E2[i]  = expf(f2);
            g_G2[i]  = expf(0.2f * f2);
        }
    }
}

// =====================================================================
// Kernel 2: fused masked-softmax-attention, fp16 mma.sync.
// 256 threads (8 warps, 2m x 4n, warp tile m16n32), BM=32, grid 256,
// __launch_bounds__(256,3) -> 3 CTAs/SM (R7 was 2/SM, latency-bound).
// SMEM: adj ring x3, sP/sB double-buffered (2nd barrier makes 2 slots safe).
// Commit order [B(ch+1)][A(ch+3)] + single wait_group 3 forces exactly
// {B(ch), A(ch+1)} while keeping 2-chunk adj prefetch depth in flight.
// =====================================================================
__device__ __forceinline__ void mma_fp16(float* c, const uint32_t* a,
                                         uint32_t b0, uint32_t b1)
{
    asm volatile(
        "mma.sync.aligned.m16n8k16.row.col.f32.f16.f16.f32 "
        "{%0,%1,%2,%3},{%4,%5,%6,%7},{%8,%9},{%0,%1,%2,%3};\n"
        : "+f"(c[0]), "+f"(c[1]), "+f"(c[2]), "+f"(c[3])
        : "r"(a[0]), "r"(a[1]), "r"(a[2]), "r"(a[3]), "r"(b0), "r"(b1));
}

#define ADJ_SLOT 8192u       // 32 x 64 ints
#define SP_SLOT  4608u       // 32 x 72 halfs
#define SB_SLOT  17408u      // 64 x 136 halfs
#define DYN_SMEM (3*ADJ_SLOT + 2*SP_SLOT + 2*SB_SLOT)   // 68608

__global__ __launch_bounds__(256, 3) void gat_main_kernel(
    const int* __restrict__ adj, float* __restrict__ out)
{
    extern __shared__ char dynsm[];
    __shared__ float sden[BM];

    const int tid  = threadIdx.x;
    const int lane = tid & 31;
    const int warp = tid >> 5;
    const int r    = tid >> 3;     // 0..31  (pgen/adj row)
    const int cb   = tid & 7;      // col block of 8
    const int i0   = blockIdx.x * BM;
    const int wm   = warp & 1;     // m16 position (2)
    const int wn   = warp >> 1;    // n32 position (4)

    const uint32_t adjS = sptr(dynsm);
    const uint32_t spS  = adjS + 3 * ADJ_SLOT;
    const uint32_t sbS  = spS  + 2 * SP_SLOT;

    const float nf1r = g_nf1[i0 + r];
    const float H1r  = g_H1 [i0 + r];
    float den = 0.0f;

    float acc[4][4];
#pragma unroll
    for (int nf = 0; nf < 4; nf++)
#pragma unroll
        for (int q = 0; q < 4; q++) acc[nf][q] = 0.0f;

    // ---- stage helpers (each always commits exactly one group) ----
    auto stage_adj = [&](int ch) {
        if (ch < NC) {
            const int* src = &adj[(size_t)(i0 + r) * NN + ch * 64 + 8 * cb];
            int sl = ch % 3;
            uint32_t dst = adjS + (uint32_t)sl * ADJ_SLOT
                         + (uint32_t)(r * 256 + 32 * cb);
            asm volatile("cp.async.cg.shared.global [%0],[%1],16;\n" :: "r"(dst), "l"(src));
            asm volatile("cp.async.cg.shared.global [%0],[%1],16;\n" :: "r"(dst+16u), "l"(src+4));
        }
        asm volatile("cp.async.commit_group;\n");
    };
    auto stage_B = [&](int ch) {
        if (ch < NC) {
            const int j0 = ch * 64;
            uint32_t base = sbS + (uint32_t)(ch & 1) * SB_SLOT;
#pragma unroll
            for (int i = 0; i < 4; i++) {
                int seg = tid + 256 * i;          // 0..1023
                int rr = seg >> 4, ss = seg & 15;
                const __half* src = &g_Wh16[(size_t)(j0 + rr) * FOUT + 8 * ss];
                uint32_t dst = base + (uint32_t)(rr * 272 + 16 * ss);
                asm volatile("cp.async.cg.shared.global [%0],[%1],16;\n" :: "r"(dst), "l"(src));
            }
        }
        asm volatile("cp.async.commit_group;\n");
    };

    auto pgen = [&](int ch) {
        const int j0 = ch * 64, c0 = 8 * cb;
        uint32_t aoff = adjS + (uint32_t)(ch % 3) * ADJ_SLOT
                      + (uint32_t)(r * 256 + 32 * cb);
        int4 a0, a1;
        asm volatile("ld.shared.v4.b32 {%0,%1,%2,%3},[%4];"
                     : "=r"(a0.x), "=r"(a0.y), "=r"(a0.z), "=r"(a0.w) : "r"(aoff));
        asm volatile("ld.shared.v4.b32 {%0,%1,%2,%3},[%4];"
                     : "=r"(a1.x), "=r"(a1.y), "=r"(a1.z), "=r"(a1.w) : "r"(aoff + 16u));
        float4 f2v0 = __ldg((const float4*)&g_f2[j0 + c0]);
        float4 f2v1 = __ldg((const float4*)&g_f2[j0 + c0 + 4]);
        float4 E2v0 = __ldg((const float4*)&g_E2[j0 + c0]);
        float4 E2v1 = __ldg((const float4*)&g_E2[j0 + c0 + 4]);
        float4 G2v0 = __ldg((const float4*)&g_G2[j0 + c0]);
        float4 G2v1 = __ldg((const float4*)&g_G2[j0 + c0 + 4]);
        float w[8];
        w[0] = (a0.x > 0) ? ((f2v0.x > nf1r) ? E2v0.x : H1r * G2v0.x) : 0.0f;
        w[1] = (a0.y > 0) ? ((f2v0.y > nf1r) ? E2v0.y : H1r * G2v0.y) : 0.0f;
        w[2] = (a0.z > 0) ? ((f2v0.z > nf1r) ? E2v0.z : H1r * G2v0.z) : 0.0f;
        w[3] = (a0.w > 0) ? ((f2v0.w > nf1r) ? E2v0.w : H1r * G2v0.w) : 0.0f;
        w[4] = (a1.x > 0) ? ((f2v1.x > nf1r) ? E2v1.x : H1r * G2v1.x) : 0.0f;
        w[5] = (a1.y > 0) ? ((f2v1.y > nf1r) ? E2v1.y : H1r * G2v1.y) : 0.0f;
        w[6] = (a1.z > 0) ? ((f2v1.z > nf1r) ? E2v1.z : H1r * G2v1.z) : 0.0f;
        w[7] = (a1.w > 0) ? ((f2v1.w > nf1r) ? E2v1.w : H1r * G2v1.w) : 0.0f;
        // no clamp needed: rescaled weights <= e^10 < fp16 max
        uint32_t u[4];
#pragma unroll
        for (int q = 0; q < 4; q++) {
            __half2 pk = __floats2half2_rn(w[2*q], w[2*q+1]);
            u[q] = *(uint32_t*)&pk;
            // denominator from the SAME fp16-rounded weights the MMA sees
            den += __low2float(pk) + __high2float(pk);
        }
        uint32_t dst = spS + (uint32_t)(ch & 1) * SP_SLOT
                     + (uint32_t)(r * 144 + c0 * 2);
        asm volatile("st.shared.v4.b32 [%0],{%1,%2,%3,%4};"
                     :: "r"(dst), "r"(u[0]), "r"(u[1]), "r"(u[2]), "r"(u[3]) : "memory");
    };

    auto mma_phase = [&](int ch) {
        uint32_t sp = spS + (uint32_t)(ch & 1) * SP_SLOT;
        uint32_t sb = sbS + (uint32_t)(ch & 1) * SB_SLOT;
        const int mi = lane >> 3, l7 = lane & 7;
        uint32_t spA = sp + (uint32_t)((16*wm + ((mi & 1) << 3) + l7) * 144
                                       + (((mi >> 1) << 3)) * 2);
        uint32_t sbB = sb + (uint32_t)((((mi & 1) << 3) + l7) * 272
                                       + (32*wn + ((mi >> 1) << 3)) * 2);
#pragma unroll
        for (int kk = 0; kk < 4; kk++) {
            uint32_t afr[4];
            asm volatile(
                "ldmatrix.sync.aligned.m8n8.x4.shared.b16 {%0,%1,%2,%3},[%4];\n"
                : "=r"(afr[0]), "=r"(afr[1]), "=r"(afr[2]), "=r"(afr[3])
                : "r"(spA + (uint32_t)(32 * kk)));
#pragma unroll
            for (int nfp = 0; nfp < 2; nfp++) {
                uint32_t b[4];
                asm volatile(
                    "ldmatrix.sync.aligned.m8n8.x4.trans.shared.b16 {%0,%1,%2,%3},[%4];\n"
                    : "=r"(b[0]), "=r"(b[1]), "=r"(b[2]), "=r"(b[3])
                    : "r"(sbB + (uint32_t)(16 * kk * 272 + 32 * nfp)));
                mma_fp16(acc[2*nfp],     afr, b[0], b[1]);
                mma_fp16(acc[2*nfp + 1], afr, b[2], b[3]);
            }
        }
    };

    // ---- prologue: commits [A0][B0][A1][A2] ----
    stage_adj(0);
    stage_B(0);
    stage_adj(1);
    stage_adj(2);
    asm volatile("cp.async.wait_group 3;\n");   // forces A0
    pgen(0);

    // ---- main loop: commits per iter [B(ch+1)][A(ch+3)] ----
    // wait_group 3 keeps {A(ch+2), B(ch+1), A(ch+3)} pending;
    // forces B(ch) (mma) and A(ch+1) (pgen). Two barriers per chunk:
    // barrier1 publishes P(ch)/B(ch); barrier2 protects 2-slot reuse.
    for (int ch = 0; ch < NC; ch++) {
        stage_B(ch + 1);
        stage_adj(ch + 3);
        asm volatile("cp.async.wait_group 3;\n");
        if (ch + 1 < NC) pgen(ch + 1);
        __syncthreads();
        mma_phase(ch);
        __syncthreads();
    }

    // ---- denominator reduction (8 threads per row) ----
    den += __shfl_xor_sync(0xffffffffu, den, 1);
    den += __shfl_xor_sync(0xffffffffu, den, 2);
    den += __shfl_xor_sync(0xffffffffu, den, 4);
    if (cb == 0) sden[r] = den;
    __syncthreads();

    // ---- epilogue: normalize, write fp32 output ----
    const int g = lane >> 2, t = lane & 3;
    {
        int row0 = 16*wm + g;
        float inv0 = 1.0f / sden[row0];
        float inv1 = 1.0f / sden[row0 + 8];
#pragma unroll
        for (int nf = 0; nf < 4; nf++) {
            int col = 32*wn + 8*nf + 2*t;
            out[(size_t)(i0 + row0)     * FOUT + col    ] = acc[nf][0] * inv0;
            out[(size_t)(i0 + row0)     * FOUT + col + 1] = acc[nf][1] * inv0;
            out[(size_t)(i0 + row0 + 8) * FOUT + col    ] = acc[nf][2] * inv1;
            out[(size_t)(i0 + row0 + 8) * FOUT + col + 1] = acc[nf][3] * inv1;
        }
    }
}

// =====================================================================
extern "C" void kernel_launch(void* const* d_in, const int* in_sizes, int n_in,
                              void* d_out, int out_size)
{
    const float* h   = (const float*)d_in[0];   // [8192,256] f32
    const int*   adj = (const int*)  d_in[1];   // [8192,8192] i32
    const float* Wm  = (const float*)d_in[2];   // [256,128] f32
    const float* a   = (const float*)d_in[3];   // [256,1] f32
    float* out = (float*)d_out;                 // [8192,128] f32

    cudaFuncSetAttribute(gat_main_kernel,
                         cudaFuncAttributeMaxDynamicSharedMemorySize, DYN_SMEM);

    wh_gemm_kernel <<<256, 256>>>(h, Wm, a);
    gat_main_kernel<<<GRID_MAIN, 256, DYN_SMEM>>>(adj, out);
}

// round 9
// speedup vs baseline: 1.0384x; 1.0384x over previous
#include <cuda_runtime.h>
#include <cuda_fp16.h>
#include <cstdint>

#define NN   8192
#define FIN  256
#define FOUT 128
#define NC   128        // j-chunks of 64
#define BM   32         // rows per CTA in main kernel
#define GRID_MAIN (NN / BM)   // 256

// ---------------- scratch (static device globals; no allocation) ----------------
__device__ __align__(16) __half g_Wh16[(size_t)NN * FOUT];  // [row j][col c] fp16
__device__ __align__(16) float g_nf1[NN];   // -f1
__device__ __align__(16) float g_H1 [NN];   // exp(-0.8 f1)
__device__ __align__(16) float g_f2 [NN];
__device__ __align__(16) float g_E2 [NN];   // exp(f2)
__device__ __align__(16) float g_G2 [NN];   // exp(0.2 f2)

__device__ __forceinline__ uint32_t sptr(const void* p) {
    return (uint32_t)__cvta_generic_to_shared(p);
}

// =====================================================================
// Kernel 1: Wh = h @ W (fp32 SIMT GEMM) fused with fp16 output and the
// f1/f2 row reductions + exp vectors. grid 256, block 256, 2 CTAs/SM.
// =====================================================================
__global__ __launch_bounds__(256, 2) void wh_gemm_kernel(
    const float* __restrict__ h, const float* __restrict__ Wm,
    const float* __restrict__ a)
{
    __shared__ float hs[32][33];
    __shared__ float Ws[32][132];
    const int tid = threadIdx.x;
    const int i0  = blockIdx.x * 32;
    const int ty  = tid >> 4, tx = tid & 15;

    float acc[2][8];
#pragma unroll
    for (int u = 0; u < 2; u++)
#pragma unroll
        for (int v = 0; v < 8; v++) acc[u][v] = 0.0f;

    for (int k0 = 0; k0 < FIN; k0 += 32) {
        __syncthreads();
        {   int r = tid >> 3, c = (tid & 7) * 4;
            float4 v = *(const float4*)&h[(size_t)(i0 + r) * FIN + k0 + c];
            hs[r][c+0]=v.x; hs[r][c+1]=v.y; hs[r][c+2]=v.z; hs[r][c+3]=v.w;
        }
        {   int r = tid >> 3, c = (tid & 7) * 16;
#pragma unroll
            for (int q = 0; q < 4; q++) {
                float4 v = *(const float4*)&Wm[(size_t)(k0 + r) * FOUT + c + 4*q];
                Ws[r][c+4*q+0]=v.x; Ws[r][c+4*q+1]=v.y; Ws[r][c+4*q+2]=v.z; Ws[r][c+4*q+3]=v.w;
            }
        }
        __syncthreads();
#pragma unroll 8
        for (int k = 0; k < 32; k++) {
            float a0 = hs[2*ty][k], a1 = hs[2*ty+1][k];
            float4 b0 = *(const float4*)&Ws[k][8*tx];
            float4 b1 = *(const float4*)&Ws[k][8*tx + 4];
            float bv[8] = {b0.x,b0.y,b0.z,b0.w,b1.x,b1.y,b1.z,b1.w};
#pragma unroll
            for (int v = 0; v < 8; v++) {
                acc[0][v] = fmaf(a0, bv[v], acc[0][v]);
                acc[1][v] = fmaf(a1, bv[v], acc[1][v]);
            }
        }
    }

    float f1a[2] = {0.f, 0.f}, f2a[2] = {0.f, 0.f};
#pragma unroll
    for (int u = 0; u < 2; u++) {
        int row = i0 + 2*ty + u;
#pragma unroll
        for (int q = 0; q < 4; q++) {
            *(__half2*)&g_Wh16[(size_t)row * FOUT + 8*tx + 2*q] =
                __floats2half2_rn(acc[u][2*q], acc[u][2*q+1]);
        }
#pragma unroll
        for (int v = 0; v < 8; v++) {
            int col = 8*tx + v;
            f1a[u] = fmaf(acc[u][v], a[col],        f1a[u]);
            f2a[u] = fmaf(acc[u][v], a[FOUT + col], f2a[u]);
        }
    }
#pragma unroll
    for (int o = 8; o > 0; o >>= 1) {
        f1a[0] += __shfl_xor_sync(0xffffffffu, f1a[0], o);
        f1a[1] += __shfl_xor_sync(0xffffffffu, f1a[1], o);
        f2a[0] += __shfl_xor_sync(0xffffffffu, f2a[0], o);
        f2a[1] += __shfl_xor_sync(0xffffffffu, f2a[1], o);
    }
    if (tx == 0) {
#pragma unroll
        for (int u = 0; u < 2; u++) {
            int i = i0 + 2*ty + u;
            float f1 = f1a[u], f2 = f2a[u];
            g_nf1[i] = -f1;
            g_H1[i]  = expf(-0.8f * f1);
            g_f2[i]  = f2;
            g_E2[i]  = expf(f2);
            g_G2[i]  = expf(0.2f * f2);
        }
    }
}

// =====================================================================
// Kernel 2: fused masked-softmax-attention, fp16 mma.sync.
// 512 threads (16 warps, warp grid 2m x 8n, warp tile m16n16), BM=32,
// grid 256. R8 lesson: occupancy was grid-limited (1.73 CTA/SM); doubling
// threads/CTA doubles warps/SM (occ 21% -> ~43%) with identical work.
// adj ring x3, sP/sB double-buffered, commit order [B(ch+1)][A(ch+3)]
// + wait_group 3; 2 barriers per chunk.
// =====================================================================
__device__ __forceinline__ void mma_fp16(float* c, const uint32_t* a,
                                         uint32_t b0, uint32_t b1)
{
    asm volatile(
        "mma.sync.aligned.m16n8k16.row.col.f32.f16.f16.f32 "
        "{%0,%1,%2,%3},{%4,%5,%6,%7},{%8,%9},{%0,%1,%2,%3};\n"
        : "+f"(c[0]), "+f"(c[1]), "+f"(c[2]), "+f"(c[3])
        : "r"(a[0]), "r"(a[1]), "r"(a[2]), "r"(a[3]), "r"(b0), "r"(b1));
}

#define ADJ_SLOT 8192u       // 32 x 64 ints
#define SP_SLOT  4608u       // 32 x 72 halfs
#define SB_SLOT  17408u      // 64 x 136 halfs
#define DYN_SMEM (3*ADJ_SLOT + 2*SP_SLOT + 2*SB_SLOT)   // 68608

__global__ __launch_bounds__(512, 2) void gat_main_kernel(
    const int* __restrict__ adj, float* __restrict__ out)
{
    extern __shared__ char dynsm[];
    __shared__ float sden[BM];

    const int tid  = threadIdx.x;
    const int lane = tid & 31;
    const int warp = tid >> 5;     // 0..15
    const int r    = tid >> 4;     // 0..31  (pgen/adj row)
    const int cq   = tid & 15;     // col group of 4
    const int i0   = blockIdx.x * BM;
    const int wm   = warp & 1;     // m16 position (2)
    const int wn   = warp >> 1;    // n16 position (8)

    const uint32_t adjS = sptr(dynsm);
    const uint32_t spS  = adjS + 3 * ADJ_SLOT;
    const uint32_t sbS  = spS  + 2 * SP_SLOT;

    const float nf1r = g_nf1[i0 + r];
    const float H1r  = g_H1 [i0 + r];
    float den = 0.0f;

    float acc[2][4];
#pragma unroll
    for (int nf = 0; nf < 2; nf++)
#pragma unroll
        for (int q = 0; q < 4; q++) acc[nf][q] = 0.0f;

    // ---- stage helpers (each always commits exactly one group) ----
    auto stage_adj = [&](int ch) {
        if (ch < NC) {
            const int* src = &adj[(size_t)(i0 + r) * NN + ch * 64 + 4 * cq];
            uint32_t dst = adjS + (uint32_t)(ch % 3) * ADJ_SLOT
                         + (uint32_t)(r * 256 + 16 * cq);
            asm volatile("cp.async.cg.shared.global [%0],[%1],16;\n" :: "r"(dst), "l"(src));
        }
        asm volatile("cp.async.commit_group;\n");
    };
    auto stage_B = [&](int ch) {
        if (ch < NC) {
            const int j0 = ch * 64;
            uint32_t base = sbS + (uint32_t)(ch & 1) * SB_SLOT;
#pragma unroll
            for (int i = 0; i < 2; i++) {
                int seg = tid + 512 * i;          // 0..1023
                int rr = seg >> 4, ss = seg & 15;
                const __half* src = &g_Wh16[(size_t)(j0 + rr) * FOUT + 8 * ss];
                uint32_t dst = base + (uint32_t)(rr * 272 + 16 * ss);
                asm volatile("cp.async.cg.shared.global [%0],[%1],16;\n" :: "r"(dst), "l"(src));
            }
        }
        asm volatile("cp.async.commit_group;\n");
    };

    auto pgen = [&](int ch) {
        const int j0 = ch * 64, c0 = 4 * cq;
        uint32_t aoff = adjS + (uint32_t)(ch % 3) * ADJ_SLOT
                      + (uint32_t)(r * 256 + 16 * cq);
        int4 a0;
        asm volatile("ld.shared.v4.b32 {%0,%1,%2,%3},[%4];"
                     : "=r"(a0.x), "=r"(a0.y), "=r"(a0.z), "=r"(a0.w) : "r"(aoff));
        float4 f2v = __ldg((const float4*)&g_f2[j0 + c0]);
        float4 E2v = __ldg((const float4*)&g_E2[j0 + c0]);
        float4 G2v = __ldg((const float4*)&g_G2[j0 + c0]);
        float w0 = (a0.x > 0) ? ((f2v.x > nf1r) ? E2v.x : H1r * G2v.x) : 0.0f;
        float w1 = (a0.y > 0) ? ((f2v.y > nf1r) ? E2v.y : H1r * G2v.y) : 0.0f;
        float w2 = (a0.z > 0) ? ((f2v.z > nf1r) ? E2v.z : H1r * G2v.z) : 0.0f;
        float w3 = (a0.w > 0) ? ((f2v.w > nf1r) ? E2v.w : H1r * G2v.w) : 0.0f;
        // no clamp needed: rescaled weights <= e^10 < fp16 max
        __half2 pk0 = __floats2half2_rn(w0, w1);
        __half2 pk1 = __floats2half2_rn(w2, w3);
        uint32_t u0 = *(uint32_t*)&pk0, u1 = *(uint32_t*)&pk1;
        // denominator from the SAME fp16-rounded weights the MMA sees
        den += __low2float(pk0) + __high2float(pk0)
             + __low2float(pk1) + __high2float(pk1);
        uint32_t dst = spS + (uint32_t)(ch & 1) * SP_SLOT
                     + (uint32_t)(r * 144 + c0 * 2);
        asm volatile("st.shared.v2.b32 [%0],{%1,%2};"
                     :: "r"(dst), "r"(u0), "r"(u1) : "memory");
    };

    auto mma_phase = [&](int ch) {
        uint32_t sp = spS + (uint32_t)(ch & 1) * SP_SLOT;
        uint32_t sb = sbS + (uint32_t)(ch & 1) * SB_SLOT;
        const int mi = lane >> 3, l7 = lane & 7;
        uint32_t spA = sp + (uint32_t)((16*wm + ((mi & 1) << 3) + l7) * 144
                                       + (((mi >> 1) << 3)) * 2);
        uint32_t sbB = sb + (uint32_t)((((mi & 1) << 3) + l7) * 272
                                       + (16*wn + ((mi >> 1) << 3)) * 2);
#pragma unroll
        for (int kk = 0; kk < 4; kk++) {
            uint32_t afr[4];
            asm volatile(
                "ldmatrix.sync.aligned.m8n8.x4.shared.b16 {%0,%1,%2,%3},[%4];\n"
                : "=r"(afr[0]), "=r"(afr[1]), "=r"(afr[2]), "=r"(afr[3])
                : "r"(spA + (uint32_t)(32 * kk)));
            uint32_t b[4];
            asm volatile(
                "ldmatrix.sync.aligned.m8n8.x4.trans.shared.b16 {%0,%1,%2,%3},[%4];\n"
                : "=r"(b[0]), "=r"(b[1]), "=r"(b[2]), "=r"(b[3])
                : "r"(sbB + (uint32_t)(16 * kk * 272)));
            mma_fp16(acc[0], afr, b[0], b[1]);
            mma_fp16(acc[1], afr, b[2], b[3]);
        }
    };

    // ---- prologue: commits [A0][B0][A1][A2] ----
    stage_adj(0);
    stage_B(0);
    stage_adj(1);
    stage_adj(2);
    asm volatile("cp.async.wait_group 3;\n");   // forces A0
    pgen(0);

    // ---- main loop: commits per iter [B(ch+1)][A(ch+3)] ----
    // wait_group 3 keeps {A(ch+2), B(ch+1), A(ch+3)} pending;
    // forces B(ch) (mma) and A(ch+1) (pgen).
    for (int ch = 0; ch < NC; ch++) {
        stage_B(ch + 1);
        stage_adj(ch + 3);
        asm volatile("cp.async.wait_group 3;\n");
        if (ch + 1 < NC) pgen(ch + 1);
        __syncthreads();
        mma_phase(ch);
        __syncthreads();
    }

    // ---- denominator reduction (16 threads per row) ----
    den += __shfl_xor_sync(0xffffffffu, den, 1);
    den += __shfl_xor_sync(0xffffffffu, den, 2);
    den += __shfl_xor_sync(0xffffffffu, den, 4);
    den += __shfl_xor_sync(0xffffffffu, den, 8);
    if (cq == 0) sden[r] = den;
    __syncthreads();

    // ---- epilogue: normalize, write fp32 output ----
    const int g = lane >> 2, t = lane & 3;
    {
        int row0 = 16*wm + g;
        float inv0 = 1.0f / sden[row0];
        float inv1 = 1.0f / sden[row0 + 8];
#pragma unroll
        for (int nf = 0; nf < 2; nf++) {
            int col = 16*wn + 8*nf + 2*t;
            out[(size_t)(i0 + row0)     * FOUT + col    ] = acc[nf][0] * inv0;
            out[(size_t)(i0 + row0)     * FOUT + col + 1] = acc[nf][1] * inv0;
            out[(size_t)(i0 + row0 + 8) * FOUT + col    ] = acc[nf][2] * inv1;
            out[(size_t)(i0 + row0 + 8) * FOUT + col + 1] = acc[nf][3] * inv1;
        }
    }
}

// =====================================================================
extern "C" void kernel_launch(void* const* d_in, const int* in_sizes, int n_in,
                              void* d_out, int out_size)
{
    const float* h   = (const float*)d_in[0];   // [8192,256] f32
    const int*   adj = (const int*)  d_in[1];   // [8192,8192] i32
    const float* Wm  = (const float*)d_in[2];   // [256,128] f32
    const float* a   = (const float*)d_in[3];   // [256,1] f32
    float* out = (float*)d_out;                 // [8192,128] f32

    cudaFuncSetAttribute(gat_main_kernel,
                         cudaFuncAttributeMaxDynamicSharedMemorySize, DYN_SMEM);

    wh_gemm_kernel <<<256, 256>>>(h, Wm, a);
    gat_main_kernel<<<GRID_MAIN, 512, DYN_SMEM>>>(adj, out);
}

// round 10
// speedup vs baseline: 1.2788x; 1.2315x over previous
#include <cuda_runtime.h>
#include <cuda_fp16.h>
#include <cstdint>

#define NN   8192
#define FIN  256
#define FOUT 128
#define NC   128        // j-chunks of 64
#define BM   32         // rows per CTA in main kernel
#define GRID_MAIN (NN / BM)   // 256

// ---------------- scratch (static device globals; no allocation) ----------------
__device__ __align__(16) __half g_Wh16[(size_t)NN * FOUT];  // [row j][col c] fp16
__device__ __align__(16) float g_nf1[NN];   // -f1
__device__ __align__(16) float g_H1 [NN];   // exp(-0.8 f1)
__device__ __align__(16) float g_f2 [NN];
__device__ __align__(16) float g_E2 [NN];   // exp(f2)
__device__ __align__(16) float g_G2 [NN];   // exp(0.2 f2)

__device__ __forceinline__ uint32_t sptr(const void* p) {
    return (uint32_t)__cvta_generic_to_shared(p);
}

// =====================================================================
// Kernel 1: Wh = h @ W (fp32 SIMT GEMM), cp.async double-buffered
// (1 barrier per k-iter, G->S overlapped with FMA). Fused fp16 output
// + f1/f2 reductions + exp vectors. grid 256, block 256, 2 CTAs/SM.
// =====================================================================
__global__ __launch_bounds__(256, 2) void wh_gemm_kernel(
    const float* __restrict__ h, const float* __restrict__ Wm,
    const float* __restrict__ a)
{
    __shared__ float hs[2][32][36];    // 144B rows (16B aligned)
    __shared__ float Ws[2][32][132];   // 528B rows (16B aligned)
    const int tid = threadIdx.x;
    const int i0  = blockIdx.x * 32;
    const int ty  = tid >> 4, tx = tid & 15;

    auto stage = [&](int kt) {
        int k0 = kt * 32, buf = kt & 1;
        {   // h tile 32x32: one 16B cp.async per thread
            int r = tid >> 3, c = (tid & 7) * 4;
            asm volatile("cp.async.cg.shared.global [%0],[%1],16;\n"
                :: "r"(sptr(&hs[buf][r][c])),
                   "l"(&h[(size_t)(i0 + r) * FIN + k0 + c]));
        }
        {   // W tile 32x128: four 16B cp.asyncs per thread
            int r = tid >> 3, c = (tid & 7) * 16;
#pragma unroll
            for (int q = 0; q < 4; q++)
                asm volatile("cp.async.cg.shared.global [%0],[%1],16;\n"
                    :: "r"(sptr(&Ws[buf][r][c + 4*q])),
                       "l"(&Wm[(size_t)(k0 + r) * FOUT + c + 4*q]));
        }
        asm volatile("cp.async.commit_group;\n");
    };

    float acc[2][8];
#pragma unroll
    for (int u = 0; u < 2; u++)
#pragma unroll
        for (int v = 0; v < 8; v++) acc[u][v] = 0.0f;

    stage(0);
    for (int kt = 0; kt < 8; kt++) {
        asm volatile("cp.async.wait_group 0;\n");
        __syncthreads();
        if (kt < 7) stage(kt + 1);
        const int buf = kt & 1;
#pragma unroll 8
        for (int k = 0; k < 32; k++) {
            float a0 = hs[buf][2*ty][k], a1 = hs[buf][2*ty+1][k];
            float4 b0 = *(const float4*)&Ws[buf][k][8*tx];
            float4 b1 = *(const float4*)&Ws[buf][k][8*tx + 4];
            float bv[8] = {b0.x,b0.y,b0.z,b0.w,b1.x,b1.y,b1.z,b1.w};
#pragma unroll
            for (int v = 0; v < 8; v++) {
                acc[0][v] = fmaf(a0, bv[v], acc[0][v]);
                acc[1][v] = fmaf(a1, bv[v], acc[1][v]);
            }
        }
    }

    float f1a[2] = {0.f, 0.f}, f2a[2] = {0.f, 0.f};
#pragma unroll
    for (int u = 0; u < 2; u++) {
        int row = i0 + 2*ty + u;
#pragma unroll
        for (int q = 0; q < 4; q++) {
            *(__half2*)&g_Wh16[(size_t)row * FOUT + 8*tx + 2*q] =
                __floats2half2_rn(acc[u][2*q], acc[u][2*q+1]);
        }
#pragma unroll
        for (int v = 0; v < 8; v++) {
            int col = 8*tx + v;
            f1a[u] = fmaf(acc[u][v], a[col],        f1a[u]);
            f2a[u] = fmaf(acc[u][v], a[FOUT + col], f2a[u]);
        }
    }
#pragma unroll
    for (int o = 8; o > 0; o >>= 1) {
        f1a[0] += __shfl_xor_sync(0xffffffffu, f1a[0], o);
        f1a[1] += __shfl_xor_sync(0xffffffffu, f1a[1], o);
        f2a[0] += __shfl_xor_sync(0xffffffffu, f2a[0], o);
        f2a[1] += __shfl_xor_sync(0xffffffffu, f2a[1], o);
    }
    if (tx == 0) {
#pragma unroll
        for (int u = 0; u < 2; u++) {
            int i = i0 + 2*ty + u;
            float f1 = f1a[u], f2 = f2a[u];
            g_nf1[i] = -f1;
            g_H1[i]  = expf(-0.8f * f1);
            g_f2[i]  = f2;
            g_E2[i]  = expf(f2);
            g_G2[i]  = expf(0.2f * f2);
        }
    }
}

// =====================================================================
// Kernel 2: fused masked-softmax-attention, fp16 mma.sync.
// 512 threads (16 warps, warp grid 2m x 8n, warp tile m16n16), BM=32,
// grid 256, 2 CTAs/SM. R9->R10: ONE barrier per chunk (3-slot sP /
// 4-slot sB / 3-slot adj make slot reuse barrier-separated), B staged
// 2 chunks ahead, pgen's j-vector loads hoisted above the wait.
// Commit order [B(ch+2)][A(ch+3)] + wait_group 4 forces {B(ch), A(ch+1)}.
// =====================================================================
__device__ __forceinline__ void mma_fp16(float* c, const uint32_t* a,
                                         uint32_t b0, uint32_t b1)
{
    asm volatile(
        "mma.sync.aligned.m16n8k16.row.col.f32.f16.f16.f32 "
        "{%0,%1,%2,%3},{%4,%5,%6,%7},{%8,%9},{%0,%1,%2,%3};\n"
        : "+f"(c[0]), "+f"(c[1]), "+f"(c[2]), "+f"(c[3])
        : "r"(a[0]), "r"(a[1]), "r"(a[2]), "r"(a[3]), "r"(b0), "r"(b1));
}

#define ADJ_SLOT 8192u       // 32 x 64 ints
#define SP_SLOT  4608u       // 32 x 72 halfs
#define SB_SLOT  17408u      // 64 x 136 halfs
#define DYN_SMEM (3*ADJ_SLOT + 3*SP_SLOT + 4*SB_SLOT)   // 108032

__global__ __launch_bounds__(512, 2) void gat_main_kernel(
    const int* __restrict__ adj, float* __restrict__ out)
{
    extern __shared__ char dynsm[];
    __shared__ float sden[BM];

    const int tid  = threadIdx.x;
    const int lane = tid & 31;
    const int warp = tid >> 5;     // 0..15
    const int r    = tid >> 4;     // 0..31  (pgen/adj row)
    const int cq   = tid & 15;     // col group of 4
    const int i0   = blockIdx.x * BM;
    const int wm   = warp & 1;     // m16 position (2)
    const int wn   = warp >> 1;    // n16 position (8)

    const uint32_t adjS = sptr(dynsm);
    const uint32_t spS  = adjS + 3 * ADJ_SLOT;
    const uint32_t sbS  = spS  + 3 * SP_SLOT;

    const float nf1r = g_nf1[i0 + r];
    const float H1r  = g_H1 [i0 + r];
    float den = 0.0f;

    float acc[2][4];
#pragma unroll
    for (int nf = 0; nf < 2; nf++)
#pragma unroll
        for (int q = 0; q < 4; q++) acc[nf][q] = 0.0f;

    // ---- stage helpers (each always commits exactly one group) ----
    auto stage_adj = [&](int ch) {
        if (ch < NC) {
            const int* src = &adj[(size_t)(i0 + r) * NN + ch * 64 + 4 * cq];
            uint32_t dst = adjS + (uint32_t)(ch % 3) * ADJ_SLOT
                         + (uint32_t)(r * 256 + 16 * cq);
            asm volatile("cp.async.cg.shared.global [%0],[%1],16;\n" :: "r"(dst), "l"(src));
        }
        asm volatile("cp.async.commit_group;\n");
    };
    auto stage_B = [&](int ch) {
        if (ch < NC) {
            const int j0 = ch * 64;
            uint32_t base = sbS + (uint32_t)(ch & 3) * SB_SLOT;
#pragma unroll
            for (int i = 0; i < 2; i++) {
                int seg = tid + 512 * i;          // 0..1023
                int rr = seg >> 4, ss = seg & 15;
                const __half* src = &g_Wh16[(size_t)(j0 + rr) * FOUT + 8 * ss];
                uint32_t dst = base + (uint32_t)(rr * 272 + 16 * ss);
                asm volatile("cp.async.cg.shared.global [%0],[%1],16;\n" :: "r"(dst), "l"(src));
            }
        }
        asm volatile("cp.async.commit_group;\n");
    };

    // pgen split: vector loads (no adj dependency) / adj-dependent rest
    auto pgen_rest = [&](int ch, float4 f2v, float4 E2v, float4 G2v) {
        const int c0 = 4 * cq;
        uint32_t aoff = adjS + (uint32_t)(ch % 3) * ADJ_SLOT
                      + (uint32_t)(r * 256 + 16 * cq);
        int4 a0;
        asm volatile("ld.shared.v4.b32 {%0,%1,%2,%3},[%4];"
                     : "=r"(a0.x), "=r"(a0.y), "=r"(a0.z), "=r"(a0.w) : "r"(aoff));
        float w0 = (a0.x > 0) ? ((f2v.x > nf1r) ? E2v.x : H1r * G2v.x) : 0.0f;
        float w1 = (a0.y > 0) ? ((f2v.y > nf1r) ? E2v.y : H1r * G2v.y) : 0.0f;
        float w2 = (a0.z > 0) ? ((f2v.z > nf1r) ? E2v.z : H1r * G2v.z) : 0.0f;
        float w3 = (a0.w > 0) ? ((f2v.w > nf1r) ? E2v.w : H1r * G2v.w) : 0.0f;
        // no clamp needed: rescaled weights <= e^10 < fp16 max
        __half2 pk0 = __floats2half2_rn(w0, w1);
        __half2 pk1 = __floats2half2_rn(w2, w3);
        uint32_t u0 = *(uint32_t*)&pk0, u1 = *(uint32_t*)&pk1;
        // denominator from the SAME fp16-rounded weights the MMA sees
        den += __low2float(pk0) + __high2float(pk0)
             + __low2float(pk1) + __high2float(pk1);
        uint32_t dst = spS + (uint32_t)(ch % 3) * SP_SLOT
                     + (uint32_t)(r * 144 + c0 * 2);
        asm volatile("st.shared.v2.b32 [%0],{%1,%2};"
                     :: "r"(dst), "r"(u0), "r"(u1) : "memory");
    };

    auto mma_phase = [&](int ch) {
        uint32_t sp = spS + (uint32_t)(ch % 3) * SP_SLOT;
        uint32_t sb = sbS + (uint32_t)(ch & 3) * SB_SLOT;
        const int mi = lane >> 3, l7 = lane & 7;
        uint32_t spA = sp + (uint32_t)((16*wm + ((mi & 1) << 3) + l7) * 144
                                       + (((mi >> 1) << 3)) * 2);
        uint32_t sbB = sb + (uint32_t)((((mi & 1) << 3) + l7) * 272
                                       + (16*wn + ((mi >> 1) << 3)) * 2);
#pragma unroll
        for (int kk = 0; kk < 4; kk++) {
            uint32_t afr[4];
            asm volatile(
                "ldmatrix.sync.aligned.m8n8.x4.shared.b16 {%0,%1,%2,%3},[%4];\n"
                : "=r"(afr[0]), "=r"(afr[1]), "=r"(afr[2]), "=r"(afr[3])
                : "r"(spA + (uint32_t)(32 * kk)));
            uint32_t b[4];
            asm volatile(
                "ldmatrix.sync.aligned.m8n8.x4.trans.shared.b16 {%0,%1,%2,%3},[%4];\n"
                : "=r"(b[0]), "=r"(b[1]), "=r"(b[2]), "=r"(b[3])
                : "r"(sbB + (uint32_t)(16 * kk * 272)));
            mma_fp16(acc[0], afr, b[0], b[1]);
            mma_fp16(acc[1], afr, b[2], b[3]);
        }
    };

    // ---- prologue: commits [A0][B0][A1][B1][A2] ----
    stage_adj(0);
    stage_B(0);
    stage_adj(1);
    stage_B(1);
    stage_adj(2);
    asm volatile("cp.async.wait_group 4;\n");   // forces A0
    {
        float4 f2v = __ldg((const float4*)&g_f2[4*cq]);
        float4 E2v = __ldg((const float4*)&g_E2[4*cq]);
        float4 G2v = __ldg((const float4*)&g_G2[4*cq]);
        pgen_rest(0, f2v, E2v, G2v);
    }

    // ---- main loop: commits per iter [B(ch+2)][A(ch+3)], 1 barrier ----
    for (int ch = 0; ch < NC; ch++) {
        stage_B(ch + 2);
        stage_adj(ch + 3);
        const int chn = ch + 1;
        float4 f2v, E2v, G2v;
        if (chn < NC) {                 // hoisted: no cp.async dependency
            f2v = __ldg((const float4*)&g_f2[chn * 64 + 4*cq]);
            E2v = __ldg((const float4*)&g_E2[chn * 64 + 4*cq]);
            G2v = __ldg((const float4*)&g_G2[chn * 64 + 4*cq]);
        }
        asm volatile("cp.async.wait_group 4;\n");   // forces B(ch), A(ch+1)
        if (chn < NC) pgen_rest(chn, f2v, E2v, G2v);
        __syncthreads();                // publishes P(ch)/B(ch); guards reuse
        mma_phase(ch);
    }

    // ---- denominator reduction (16 threads per row) ----
    den += __shfl_xor_sync(0xffffffffu, den, 1);
    den += __shfl_xor_sync(0xffffffffu, den, 2);
    den += __shfl_xor_sync(0xffffffffu, den, 4);
    den += __shfl_xor_sync(0xffffffffu, den, 8);
    if (cq == 0) sden[r] = den;
    __syncthreads();

    // ---- epilogue: normalize, write fp32 output ----
    const int g = lane >> 2, t = lane & 3;
    {
        int row0 = 16*wm + g;
        float inv0 = 1.0f / sden[row0];
        float inv1 = 1.0f / sden[row0 + 8];
#pragma unroll
        for (int nf = 0; nf < 2; nf++) {
            int col = 16*wn + 8*nf + 2*t;
            out[(size_t)(i0 + row0)     * FOUT + col    ] = acc[nf][0] * inv0;
            out[(size_t)(i0 + row0)     * FOUT + col + 1] = acc[nf][1] * inv0;
            out[(size_t)(i0 + row0 + 8) * FOUT + col    ] = acc[nf][2] * inv1;
            out[(size_t)(i0 + row0 + 8) * FOUT + col + 1] = acc[nf][3] * inv1;
        }
    }
}

// =====================================================================
extern "C" void kernel_launch(void* const* d_in, const int* in_sizes, int n_in,
                              void* d_out, int out_size)
{
    const float* h   = (const float*)d_in[0];   // [8192,256] f32
    const int*   adj = (const int*)  d_in[1];   // [8192,8192] i32
    const float* Wm  = (const float*)d_in[2];   // [256,128] f32
    const float* a   = (const float*)d_in[3];   // [256,1] f32
    float* out = (float*)d_out;                 // [8192,128] f32

    cudaFuncSetAttribute(gat_main_kernel,
                         cudaFuncAttributeMaxDynamicSharedMemorySize, DYN_SMEM);

    wh_gemm_kernel <<<256, 256>>>(h, Wm, a);
    gat_main_kernel<<<GRID_MAIN, 512, DYN_SMEM>>>(adj, out);
}